// round 14
// baseline (speedup 1.0000x reference)
#include <cuda_runtime.h>
#include <cuda_bf16.h>
#include <cstdint>
#include <math.h>

// Problem constants (fixed by the dataset)
#define D_MODEL   1024
#define HEADS     16
#define HEAD_DIM  64
#define BATCH     2
#define SEQ       2048
#define M_TOTAL   (BATCH * SEQ)       // 4096 rows for projection GEMMs

// Scratch: device globals (no allocations allowed). All activations/weights
// are kept as hi/lo bf16 split pairs (sum ~= fp32 value, err ~2^-18).
__device__ __nv_bfloat16 g_xh[M_TOTAL * D_MODEL];
__device__ __nv_bfloat16 g_xl[M_TOTAL * D_MODEL];
__device__ __nv_bfloat16 g_yh[M_TOTAL * D_MODEL];
__device__ __nv_bfloat16 g_yl[M_TOTAL * D_MODEL];
__device__ __nv_bfloat16 g_wqh[D_MODEL * D_MODEL];
__device__ __nv_bfloat16 g_wql[D_MODEL * D_MODEL];
__device__ __nv_bfloat16 g_wkh[D_MODEL * D_MODEL];
__device__ __nv_bfloat16 g_wkl[D_MODEL * D_MODEL];
__device__ __nv_bfloat16 g_wvh[D_MODEL * D_MODEL];
__device__ __nv_bfloat16 g_wvl[D_MODEL * D_MODEL];
__device__ __nv_bfloat16 g_woh[D_MODEL * D_MODEL];
__device__ __nv_bfloat16 g_wol[D_MODEL * D_MODEL];
__device__ __nv_bfloat16 g_qh[M_TOTAL * D_MODEL];
__device__ __nv_bfloat16 g_ql[M_TOTAL * D_MODEL];
__device__ __nv_bfloat16 g_kh[M_TOTAL * D_MODEL];
__device__ __nv_bfloat16 g_kl[M_TOTAL * D_MODEL];
__device__ __nv_bfloat16 g_vh[M_TOTAL * D_MODEL];
__device__ __nv_bfloat16 g_vl[M_TOTAL * D_MODEL];
__device__ __nv_bfloat16 g_ah[M_TOTAL * D_MODEL];
__device__ __nv_bfloat16 g_al[M_TOTAL * D_MODEL];

// ============================================================================
// Warp-level MMA helpers (mma.sync + ldmatrix + cp.async — base sm_103)
// ============================================================================
__device__ __forceinline__ uint32_t smem_u32(const void* p) {
    uint32_t a;
    asm("{ .reg .u64 t; cvta.to.shared.u64 t, %1; cvt.u32.u64 %0, t; }"
        : "=r"(a) : "l"(p));
    return a;
}

__device__ __forceinline__ void ldm_x4(uint32_t* r, uint32_t addr) {
    asm volatile("ldmatrix.sync.aligned.m8n8.x4.shared.b16 {%0,%1,%2,%3}, [%4];"
                 : "=r"(r[0]), "=r"(r[1]), "=r"(r[2]), "=r"(r[3]) : "r"(addr));
}

__device__ __forceinline__ void ldm_x4_trans(uint32_t* r, uint32_t addr) {
    asm volatile("ldmatrix.sync.aligned.m8n8.x4.trans.shared.b16 {%0,%1,%2,%3}, [%4];"
                 : "=r"(r[0]), "=r"(r[1]), "=r"(r[2]), "=r"(r[3]) : "r"(addr));
}

// D += A(16x16) * B(16x8)  bf16 inputs, fp32 accum
__device__ __forceinline__ void mma16816(float* d, const uint32_t* a, const uint32_t* b) {
    asm volatile(
        "mma.sync.aligned.m16n8k16.row.col.f32.bf16.bf16.f32 "
        "{%0,%1,%2,%3}, {%4,%5,%6,%7}, {%8,%9}, {%0,%1,%2,%3};"
        : "+f"(d[0]), "+f"(d[1]), "+f"(d[2]), "+f"(d[3])
        : "r"(a[0]), "r"(a[1]), "r"(a[2]), "r"(a[3]), "r"(b[0]), "r"(b[1]));
}

__device__ __forceinline__ void cpa16(uint32_t dst, const void* src) {
    asm volatile("cp.async.ca.shared.global [%0], [%1], 16;"
                 :: "r"(dst), "l"(src) : "memory");
}
#define CP_COMMIT() asm volatile("cp.async.commit_group;" ::: "memory")
#define CP_WAIT0()  asm volatile("cp.async.wait_group 0;" ::: "memory")

// 4 fp32 -> 4 bf16 hi + 4 bf16 lo (residual) as packed pairs
__device__ __forceinline__ void split4(float4 v, uint32_t& h01, uint32_t& h23,
                                       uint32_t& l01, uint32_t& l23) {
    asm("cvt.rn.bf16x2.f32 %0, %1, %2;" : "=r"(h01) : "f"(v.y), "f"(v.x));
    asm("cvt.rn.bf16x2.f32 %0, %1, %2;" : "=r"(h23) : "f"(v.w), "f"(v.z));
    float r0 = v.x - __uint_as_float(h01 << 16);
    float r1 = v.y - __uint_as_float(h01 & 0xFFFF0000u);
    float r2 = v.z - __uint_as_float(h23 << 16);
    float r3 = v.w - __uint_as_float(h23 & 0xFFFF0000u);
    asm("cvt.rn.bf16x2.f32 %0, %1, %2;" : "=r"(l01) : "f"(r1), "f"(r0));
    asm("cvt.rn.bf16x2.f32 %0, %1, %2;" : "=r"(l23) : "f"(r3), "f"(r2));
}

// Pack two fp32 -> bf16x2 (lo half = first arg) + residual pair
__device__ __forceinline__ void pack_split(float p0, float p1, uint32_t& h, uint32_t& l) {
    asm("cvt.rn.bf16x2.f32 %0, %1, %2;" : "=r"(h) : "f"(p1), "f"(p0));
    float r0 = p0 - __uint_as_float(h << 16);
    float r1 = p1 - __uint_as_float(h & 0xFFFF0000u);
    asm("cvt.rn.bf16x2.f32 %0, %1, %2;" : "=r"(l) : "f"(r1), "f"(r0));
}

// ============================================================================
// Prepass: elementwise fp32 -> hi/lo bf16 split. ONE launch; blockIdx.y
// selects the tensor (0:x 1:y 2:Wq 3:Wk 4:Wv 5:Wo).
// ============================================================================
#define NX4 (M_TOTAL * D_MODEL / 4)     // 1048576
#define NW4 (D_MODEL * D_MODEL / 4)     // 262144

__global__ __launch_bounds__(256) void split_all(
    const float* __restrict__ x,  const float* __restrict__ y,
    const float* __restrict__ wq, const float* __restrict__ wk,
    const float* __restrict__ wv, const float* __restrict__ wo)
{
    const int t = blockIdx.y;
    const float* src;
    __nv_bfloat16 *hi, *lo;
    int n4;
    switch (t) {
        case 0:  src = x;  hi = g_xh;  lo = g_xl;  n4 = NX4; break;
        case 1:  src = y;  hi = g_yh;  lo = g_yl;  n4 = NX4; break;
        case 2:  src = wq; hi = g_wqh; lo = g_wql; n4 = NW4; break;
        case 3:  src = wk; hi = g_wkh; lo = g_wkl; n4 = NW4; break;
        case 4:  src = wv; hi = g_wvh; lo = g_wvl; n4 = NW4; break;
        default: src = wo; hi = g_woh; lo = g_wol; n4 = NW4; break;
    }
    int i = blockIdx.x * 256 + threadIdx.x;
    if (i >= n4) return;
    float4 v = ((const float4*)src)[i];
    uint32_t h01, h23, l01, l23;
    split4(v, h01, h23, l01, l23);
    ((uint2*)hi)[i] = make_uint2(h01, h23);
    ((uint2*)lo)[i] = make_uint2(l01, l23);
}

// ============================================================================
// GEMM body v2: C[M,N] = A[M,K] @ W[N,K]^T + bias   (M=4096, N=K=1024)
// CTA tile 128x64, BK=16, 8 warps in 4x2, warp tile 32x32 (acc = 32 regs).
// 3 CTAs/SM (regs<=85, smem 36.9KB). cp.async double-buffered, 1 barrier/iter.
// ============================================================================
#define BM 128
#define BN 64
#define BK 16
#define KITERS (D_MODEL / BK)       // 64
#define LDTB 48                      // tile row stride bytes (16 halves + pad)
#define GT_AH 0                      // 128*48 = 6144
#define GT_AL 6144
#define GT_BH 12288                  // 64*48 = 3072
#define GT_BL 15360
#define GBUF  18432
#define GEMM_SMEM (2 * GBUF)         // 36864

template<bool SPLIT>
__device__ __forceinline__ void gemm_body(
    const __nv_bfloat16* __restrict__ Ahi, const __nv_bfloat16* __restrict__ Alo,
    const __nv_bfloat16* __restrict__ Whi, const __nv_bfloat16* __restrict__ Wlo,
    const float* __restrict__ bias,
    float* __restrict__ C,
    __nv_bfloat16* __restrict__ Chi,
    __nv_bfloat16* __restrict__ Clo,
    uint32_t smb)
{
    const int tid    = threadIdx.x;
    const int lane   = tid & 31;
    const int wid    = tid >> 5;
    const int warp_m = wid & 3;          // 4 warps along M (32 rows each)
    const int warp_n = wid >> 2;         // 2 warps along N (32 cols each)
    const int bm     = blockIdx.y;
    const int bn     = blockIdx.x;

    const __nv_bfloat16* Ah = Ahi + (size_t)bm * BM * D_MODEL;
    const __nv_bfloat16* Al = Alo + (size_t)bm * BM * D_MODEL;
    const __nv_bfloat16* Wh = Whi + (size_t)bn * BN * D_MODEL;
    const __nv_bfloat16* Wl = Wlo + (size_t)bn * BN * D_MODEL;

    // Staging: A has 128 rows x 2 16B-chunks = 256 chunks -> 1/thread (hi,lo).
    // B has 64 rows x 2 chunks = 128 chunks -> tid>>1 picks chunk, tid&1 hi/lo.
    const int ar = tid >> 1, ac = tid & 1;
    const uint32_t a_so = (uint32_t)(ar * LDTB + ac * 16);
    const uint32_t a_go = (uint32_t)(ar * D_MODEL + ac * 8);
    const int br = tid >> 2, bc = (tid >> 1) & 1;
    const uint32_t b_so = (uint32_t)(br * LDTB + bc * 16);
    const uint32_t b_go = (uint32_t)(br * D_MODEL + bc * 8);
    const __nv_bfloat16* Bsrc = (tid & 1) ? Wl : Wh;
    const uint32_t b_dst = (tid & 1) ? GT_BL : GT_BH;

    // ldmatrix offsets (validated R5 A pattern; B spans two n8 groups)
    const uint32_t a_off =
        (uint32_t)((warp_m * 32 + (lane & 7) + ((lane >> 3) & 1) * 8) * LDTB
                   + (lane >> 4) * 16);
    const uint32_t b_off =
        (uint32_t)((warp_n * 32 + (lane & 7) + ((lane >> 4) & 1) * 8) * LDTB
                   + ((lane >> 3) & 1) * 16);

    float acc[2][4][4];                  // [mt][nt][frag]
    #pragma unroll
    for (int mt = 0; mt < 2; mt++)
        #pragma unroll
        for (int nt = 0; nt < 4; nt++)
            #pragma unroll
            for (int j = 0; j < 4; j++) acc[mt][nt][j] = 0.0f;

    // Stage k-tile 0 into buffer 0
    cpa16(smb + GT_AH + a_so, Ah + a_go);
    cpa16(smb + GT_AL + a_so, Al + a_go);
    cpa16(smb + b_dst + b_so, Bsrc + b_go);
    CP_COMMIT();

    for (int it = 0; it < KITERS; it++) {
        CP_WAIT0();
        __syncthreads();
        if (it + 1 < KITERS) {
            const uint32_t nb = smb + ((it + 1) & 1) * GBUF;
            const uint32_t g = (uint32_t)((it + 1) * BK);
            cpa16(nb + GT_AH + a_so, Ah + a_go + g);
            cpa16(nb + GT_AL + a_so, Al + a_go + g);
            cpa16(nb + b_dst + b_so, Bsrc + b_go + g);
            CP_COMMIT();
        }
        const uint32_t bufb = smb + (it & 1) * GBUF;

        // A fragments: m16 x k16 per x4; mt in {0,1}
        uint32_t ah[2][4], al[2][4];
        #pragma unroll
        for (int mt = 0; mt < 2; mt++) {
            uint32_t off = a_off + (uint32_t)(mt * 16 * LDTB);
            ldm_x4(ah[mt], bufb + GT_AH + off);
            ldm_x4(al[mt], bufb + GT_AL + off);
        }

        // B fragments: n16 x k16 per x4; ntp in {0,1} covers n32
        #pragma unroll
        for (int ntp = 0; ntp < 2; ntp++) {
            uint32_t off = b_off + (uint32_t)(ntp * 16 * LDTB);
            uint32_t bh[4], bl[4];
            ldm_x4(bh, bufb + GT_BH + off);
            ldm_x4(bl, bufb + GT_BL + off);
            #pragma unroll
            for (int sub = 0; sub < 2; sub++) {
                const int nt = ntp * 2 + sub;
                #pragma unroll
                for (int mt = 0; mt < 2; mt++) {
                    mma16816(acc[mt][nt], ah[mt], bh + sub * 2);
                    mma16816(acc[mt][nt], ah[mt], bl + sub * 2);
                    mma16816(acc[mt][nt], al[mt], bh + sub * 2);
                }
            }
        }
    }

    const int lrow = lane >> 2;
    const int lcol = (lane & 3) * 2;
    #pragma unroll
    for (int mt = 0; mt < 2; mt++) {
        const int r0 = bm * BM + warp_m * 32 + mt * 16 + lrow;
        #pragma unroll
        for (int nt = 0; nt < 4; nt++) {
            const int cg = bn * BN + warp_n * 32 + nt * 8 + lcol;
            const float b0 = bias[cg], b1 = bias[cg + 1];
            float c00 = acc[mt][nt][0] + b0, c01 = acc[mt][nt][1] + b1;
            float c10 = acc[mt][nt][2] + b0, c11 = acc[mt][nt][3] + b1;
            if (SPLIT) {
                uint32_t h0, l0, h1, l1;
                pack_split(c00, c01, h0, l0);
                pack_split(c10, c11, h1, l1);
                *(uint32_t*)(Chi + (size_t)r0 * D_MODEL + cg)       = h0;
                *(uint32_t*)(Clo + (size_t)r0 * D_MODEL + cg)       = l0;
                *(uint32_t*)(Chi + (size_t)(r0 + 8) * D_MODEL + cg) = h1;
                *(uint32_t*)(Clo + (size_t)(r0 + 8) * D_MODEL + cg) = l1;
            } else {
                *(float2*)(C + (size_t)r0 * D_MODEL + cg)       = make_float2(c00, c01);
                *(float2*)(C + (size_t)(r0 + 8) * D_MODEL + cg) = make_float2(c10, c11);
            }
        }
    }
}

// Fused Q/K/V projection: blockIdx.z selects which GEMM this CTA computes.
__global__ void __launch_bounds__(256, 3) gemm_qkv(
    const float* __restrict__ bq,
    const float* __restrict__ bk,
    const float* __restrict__ bv)
{
    extern __shared__ char sm[];
    const uint32_t smb = smem_u32(sm);
    const int z = blockIdx.z;
    if (z == 0) {
        gemm_body<true>(g_xh, g_xl, g_wqh, g_wql, bq, nullptr, g_qh, g_ql, smb);
    } else if (z == 1) {
        gemm_body<true>(g_yh, g_yl, g_wkh, g_wkl, bk, nullptr, g_kh, g_kl, smb);
    } else {
        gemm_body<true>(g_yh, g_yl, g_wvh, g_wvl, bv, nullptr, g_vh, g_vl, smb);
    }
}

// Output projection: attn (pre-split) @ Wo^T + bo -> fp32 out
__global__ void __launch_bounds__(256, 3) gemm_o(
    const float* __restrict__ bo, float* __restrict__ out)
{
    extern __shared__ char sm[];
    const uint32_t smb = smem_u32(sm);
    gemm_body<false>(g_ah, g_al, g_woh, g_wol, bo, out, nullptr, nullptr, smb);
}

// ============================================================================
// Flash attention on tensor cores. Inputs pre-split bf16 hi/lo; output written
// pre-split for the O-projection. [validated R11 body]
// ============================================================================
#define LDB     144                  // smem row stride bytes (72 halves)
#define KV_KH   0
#define KV_KL   9216
#define KV_VH   18432
#define KV_VL   27648
#define KVBUF   36864                // per-buffer size
#define OFF_QH  KVBUF                // Q staged in buffer 1, recycled after hoist
#define OFF_QL  (KVBUF + 18432)
#define ATT_SMEM (2 * KVBUF)         // 73728

__device__ __forceinline__ void stage_kv_tile(
    uint32_t bufb,
    const __nv_bfloat16* kh, const __nv_bfloat16* kl,
    const __nv_bfloat16* vh, const __nv_bfloat16* vl,
    int tid)
{
    #pragma unroll
    for (int i = 0; i < 2; i++) {
        int f = tid + i * 256;
        int r = f >> 3, c = f & 7;
        uint32_t so = (uint32_t)(r * LDB + c * 16);
        size_t go = (size_t)r * D_MODEL + c * 8;
        cpa16(bufb + KV_KH + so, kh + go);
        cpa16(bufb + KV_KL + so, kl + go);
        cpa16(bufb + KV_VH + so, vh + go);
        cpa16(bufb + KV_VL + so, vl + go);
    }
}

__global__ void __launch_bounds__(256, 2) flash_attn_mma(const float* __restrict__ mask)
{
    extern __shared__ char sm[];
    const uint32_t smb = smem_u32(sm);
    const int tid  = threadIdx.x;
    const int lane = tid & 31;
    const int wid  = tid >> 5;
    const int bh   = blockIdx.x;
    const int b    = bh >> 4;            // / HEADS
    const int h    = bh & 15;
    const int q0   = blockIdx.y * 128;

    const size_t qrow0 = (size_t)(b * SEQ + q0);
    const size_t krow0 = (size_t)b * SEQ;
    const __nv_bfloat16* Qh = g_qh + qrow0 * D_MODEL + h * HEAD_DIM;
    const __nv_bfloat16* Ql = g_ql + qrow0 * D_MODEL + h * HEAD_DIM;
    const __nv_bfloat16* Kh = g_kh + krow0 * D_MODEL + h * HEAD_DIM;
    const __nv_bfloat16* Kl = g_kl + krow0 * D_MODEL + h * HEAD_DIM;
    const __nv_bfloat16* Vh = g_vh + krow0 * D_MODEL + h * HEAD_DIM;
    const __nv_bfloat16* Vl = g_vl + krow0 * D_MODEL + h * HEAD_DIM;
    const float* Mg = mask + (qrow0) * SEQ;

    // Stage Q (into buffer-1 region) + KV tile 0 (buffer 0)
    #pragma unroll
    for (int i = 0; i < 4; i++) {
        int f = tid + i * 256;
        int r = f >> 3, c = f & 7;
        uint32_t so = (uint32_t)(r * LDB + c * 16);
        size_t go = (size_t)r * D_MODEL + c * 8;
        cpa16(smb + OFF_QH + so, Qh + go);
        cpa16(smb + OFF_QL + so, Ql + go);
    }
    stage_kv_tile(smb, Kh, Kl, Vh, Vl, tid);
    CP_COMMIT();
    CP_WAIT0();
    __syncthreads();

    // Hoist Q fragments to registers (whole KV loop)
    const int qr = wid * 16;
    uint32_t ah[4][4], al[4][4];
    {
        uint32_t base = smb + (uint32_t)((qr + (lane & 15)) * LDB + (lane >> 4) * 16);
        #pragma unroll
        for (int ks = 0; ks < 4; ks++) {
            ldm_x4(ah[ks], base + OFF_QH + ks * 32);
            ldm_x4(al[ks], base + OFF_QL + ks * 32);
        }
    }
    __syncthreads();   // everyone done reading Q smem; buffer 1 is now free

    // Prefetch KV tile 1 into buffer 1 (recycled Q region)
    stage_kv_tile(smb + KVBUF, Kh + 64 * D_MODEL, Kl + 64 * D_MODEL,
                  Vh + 64 * D_MODEL, Vl + 64 * D_MODEL, tid);
    CP_COMMIT();

    const int lrow = lane >> 2;
    const int lcol = (lane & 3) * 2;
    const uint32_t kfrag = (uint32_t)((lane & 7) * LDB + (lane >> 3) * 16);

    float o[8][4];
    #pragma unroll
    for (int dt = 0; dt < 8; dt++)
        #pragma unroll
        for (int j = 0; j < 4; j++) o[dt][j] = 0.0f;
    float m0 = -1e30f, m8 = -1e30f, l0 = 0.0f, l8 = 0.0f;

    for (int kb = 0; kb < SEQ / 64; kb++) {
        if (kb > 0) {
            CP_WAIT0();
            __syncthreads();
        }
        if (kb >= 1 && kb + 1 < SEQ / 64) {
            size_t off = (size_t)(kb + 1) * 64 * D_MODEL;
            stage_kv_tile(smb + ((kb + 1) & 1) * KVBUF,
                          Kh + off, Kl + off, Vh + off, Vl + off, tid);
            CP_COMMIT();
        }
        const uint32_t bufb = smb + (kb & 1) * KVBUF;

        // S = Q K^T (3-pass hi/lo), warp tile 16x64
        float s[8][4];
        #pragma unroll
        for (int nt = 0; nt < 8; nt++)
            #pragma unroll
            for (int j = 0; j < 4; j++) s[nt][j] = 0.0f;

        #pragma unroll
        for (int nt = 0; nt < 8; nt++) {
            uint32_t ka = bufb + kfrag + (uint32_t)(nt * 8 * LDB);
            uint32_t kh[8], kl[8];
            ldm_x4(kh,     ka + KV_KH);
            ldm_x4(kh + 4, ka + KV_KH + 64);
            ldm_x4(kl,     ka + KV_KL);
            ldm_x4(kl + 4, ka + KV_KL + 64);
            #pragma unroll
            for (int ks = 0; ks < 4; ks++) {
                mma16816(s[nt], ah[ks], kh + ks * 2);
                mma16816(s[nt], ah[ks], kl + ks * 2);
                mma16816(s[nt], al[ks], kh + ks * 2);
            }
        }

        // Scale + mask + row max
        const float* mrow = Mg + (size_t)kb * 64;
        float tmax0 = -1e30f, tmax8 = -1e30f;
        #pragma unroll
        for (int nt = 0; nt < 8; nt++) {
            int c = nt * 8 + lcol;
            float2 mk0 = *(const float2*)(mrow + (size_t)(qr + lrow) * SEQ + c);
            float2 mk8 = *(const float2*)(mrow + (size_t)(qr + lrow + 8) * SEQ + c);
            s[nt][0] = fmaf(s[nt][0], 0.125f, (mk0.x - 1.0f) * 1e9f);
            s[nt][1] = fmaf(s[nt][1], 0.125f, (mk0.y - 1.0f) * 1e9f);
            s[nt][2] = fmaf(s[nt][2], 0.125f, (mk8.x - 1.0f) * 1e9f);
            s[nt][3] = fmaf(s[nt][3], 0.125f, (mk8.y - 1.0f) * 1e9f);
            tmax0 = fmaxf(tmax0, fmaxf(s[nt][0], s[nt][1]));
            tmax8 = fmaxf(tmax8, fmaxf(s[nt][2], s[nt][3]));
        }
        tmax0 = fmaxf(tmax0, __shfl_xor_sync(0xffffffffu, tmax0, 1));
        tmax0 = fmaxf(tmax0, __shfl_xor_sync(0xffffffffu, tmax0, 2));
        tmax8 = fmaxf(tmax8, __shfl_xor_sync(0xffffffffu, tmax8, 1));
        tmax8 = fmaxf(tmax8, __shfl_xor_sync(0xffffffffu, tmax8, 2));

        float mn0 = fmaxf(m0, tmax0), mn8 = fmaxf(m8, tmax8);
        float al0 = __expf(m0 - mn0), al8 = __expf(m8 - mn8);
        m0 = mn0; m8 = mn8;

        // exp, sums, and P fragments (hi/lo) in registers
        float sum0 = 0.0f, sum8 = 0.0f;
        uint32_t pah[4][4], pal[4][4];
        #pragma unroll
        for (int nt = 0; nt < 8; nt++) {
            float p0 = __expf(s[nt][0] - mn0);
            float p1 = __expf(s[nt][1] - mn0);
            float p2 = __expf(s[nt][2] - mn8);
            float p3 = __expf(s[nt][3] - mn8);
            sum0 += p0 + p1;
            sum8 += p2 + p3;
            int ks = nt >> 1, slot = (nt & 1) * 2;
            pack_split(p0, p1, pah[ks][slot],     pal[ks][slot]);
            pack_split(p2, p3, pah[ks][slot + 1], pal[ks][slot + 1]);
        }
        sum0 += __shfl_xor_sync(0xffffffffu, sum0, 1);
        sum0 += __shfl_xor_sync(0xffffffffu, sum0, 2);
        sum8 += __shfl_xor_sync(0xffffffffu, sum8, 1);
        sum8 += __shfl_xor_sync(0xffffffffu, sum8, 2);
        l0 = l0 * al0 + sum0;
        l8 = l8 * al8 + sum8;

        // Rescale O, then O += P @ V (3-pass hi/lo, V via ldmatrix.trans)
        #pragma unroll
        for (int dt = 0; dt < 8; dt++) {
            o[dt][0] *= al0; o[dt][1] *= al0;
            o[dt][2] *= al8; o[dt][3] *= al8;
        }
        #pragma unroll
        for (int dt = 0; dt < 8; dt++) {
            uint32_t va = bufb + (uint32_t)(lane * LDB + dt * 16);
            uint32_t vh[8], vl[8];
            ldm_x4_trans(vh,     va + KV_VH);
            ldm_x4_trans(vh + 4, va + KV_VH + 32 * LDB);
            ldm_x4_trans(vl,     va + KV_VL);
            ldm_x4_trans(vl + 4, va + KV_VL + 32 * LDB);
            #pragma unroll
            for (int ks = 0; ks < 4; ks++) {
                mma16816(o[dt], pah[ks], vh + ks * 2);
                mma16816(o[dt], pah[ks], vl + ks * 2);
                mma16816(o[dt], pal[ks], vh + ks * 2);
            }
        }
    }

    // Normalize and store pre-split (hi/lo) for the O-projection
    const float inv0 = 1.0f / l0;
    const float inv8 = 1.0f / l8;
    const size_t orow = (qrow0 + qr + lrow) * D_MODEL + h * HEAD_DIM;
    #pragma unroll
    for (int dt = 0; dt < 8; dt++) {
        int c = dt * 8 + lcol;
        uint32_t h0, l0r, h1, l1r;
        pack_split(o[dt][0] * inv0, o[dt][1] * inv0, h0, l0r);
        pack_split(o[dt][2] * inv8, o[dt][3] * inv8, h1, l1r);
        *(uint32_t*)(g_ah + orow + c)               = h0;
        *(uint32_t*)(g_al + orow + c)               = l0r;
        *(uint32_t*)(g_ah + orow + 8 * D_MODEL + c) = h1;
        *(uint32_t*)(g_al + orow + 8 * D_MODEL + c) = l1r;
    }
}

// ----------------------------------------------------------------------------
extern "C" void kernel_launch(void* const* d_in, const int* in_sizes, int n_in,
                              void* d_out, int out_size)
{
    const float* x    = (const float*)d_in[0];
    const float* y    = (const float*)d_in[1];
    const float* mask = (const float*)d_in[2];
    const float* Wq   = (const float*)d_in[3];
    const float* bq   = (const float*)d_in[4];
    const float* Wk   = (const float*)d_in[5];
    const float* bk   = (const float*)d_in[6];
    const float* Wv   = (const float*)d_in[7];
    const float* bv   = (const float*)d_in[8];
    const float* Wo   = (const float*)d_in[9];
    const float* bo   = (const float*)d_in[10];
    float* out = (float*)d_out;

    cudaFuncSetAttribute(gemm_qkv,
                         cudaFuncAttributeMaxDynamicSharedMemorySize, GEMM_SMEM);
    cudaFuncSetAttribute(gemm_o,
                         cudaFuncAttributeMaxDynamicSharedMemorySize, GEMM_SMEM);
    cudaFuncSetAttribute(flash_attn_mma,
                         cudaFuncAttributeMaxDynamicSharedMemorySize, ATT_SMEM);

    // Prepass: split x, y, and the 4 weight matrices (one launch)
    dim3 sgrid(NX4 / 256, 6);
    split_all<<<sgrid, 256>>>(x, y, Wq, Wk, Wv, Wo);

    // Fused Q/K/V projections (one launch, 1536 CTAs)
    dim3 ggrid(D_MODEL / BN, M_TOTAL / BM, 3);   // (16, 32, 3)
    gemm_qkv<<<ggrid, 256, GEMM_SMEM>>>(bq, bk, bv);

    // Attention
    dim3 agrid(BATCH * HEADS, SEQ / 128);        // (32, 16)
    flash_attn_mma<<<agrid, 256, ATT_SMEM>>>(mask);

    // Output projection
    dim3 ogrid(D_MODEL / BN, M_TOTAL / BM);      // (16, 32)
    gemm_o<<<ogrid, 256, GEMM_SMEM>>>(bo, out);
}

// round 15
// speedup vs baseline: 1.0669x; 1.0669x over previous
#include <cuda_runtime.h>
#include <cuda_bf16.h>
#include <cstdint>
#include <math.h>

// Problem constants (fixed by the dataset)
#define D_MODEL   1024
#define HEADS     16
#define HEAD_DIM  64
#define BATCH     2
#define SEQ       2048
#define M_TOTAL   (BATCH * SEQ)       // 4096 rows for projection GEMMs

// Scratch: device globals (no allocations allowed). All activations/weights
// are kept as hi/lo bf16 split pairs (sum ~= fp32 value, err ~2^-18).
__device__ __nv_bfloat16 g_xh[M_TOTAL * D_MODEL];
__device__ __nv_bfloat16 g_xl[M_TOTAL * D_MODEL];
__device__ __nv_bfloat16 g_yh[M_TOTAL * D_MODEL];
__device__ __nv_bfloat16 g_yl[M_TOTAL * D_MODEL];
__device__ __nv_bfloat16 g_wqh[D_MODEL * D_MODEL];
__device__ __nv_bfloat16 g_wql[D_MODEL * D_MODEL];
__device__ __nv_bfloat16 g_wkh[D_MODEL * D_MODEL];
__device__ __nv_bfloat16 g_wkl[D_MODEL * D_MODEL];
__device__ __nv_bfloat16 g_wvh[D_MODEL * D_MODEL];
__device__ __nv_bfloat16 g_wvl[D_MODEL * D_MODEL];
__device__ __nv_bfloat16 g_woh[D_MODEL * D_MODEL];
__device__ __nv_bfloat16 g_wol[D_MODEL * D_MODEL];
__device__ __nv_bfloat16 g_qh[M_TOTAL * D_MODEL];
__device__ __nv_bfloat16 g_ql[M_TOTAL * D_MODEL];
__device__ __nv_bfloat16 g_kh[M_TOTAL * D_MODEL];
__device__ __nv_bfloat16 g_kl[M_TOTAL * D_MODEL];
__device__ __nv_bfloat16 g_vh[M_TOTAL * D_MODEL];
__device__ __nv_bfloat16 g_vl[M_TOTAL * D_MODEL];
__device__ __nv_bfloat16 g_ah[M_TOTAL * D_MODEL];
__device__ __nv_bfloat16 g_al[M_TOTAL * D_MODEL];
// Mask bias: (mask - 1) * 1e9, bf16 (0 / -1e9 exactly representable)
__device__ __nv_bfloat16 g_mb[BATCH * SEQ * SEQ];

// ============================================================================
// Warp-level MMA helpers (mma.sync + ldmatrix + cp.async — base sm_103)
// ============================================================================
__device__ __forceinline__ uint32_t smem_u32(const void* p) {
    uint32_t a;
    asm("{ .reg .u64 t; cvta.to.shared.u64 t, %1; cvt.u32.u64 %0, t; }"
        : "=r"(a) : "l"(p));
    return a;
}

__device__ __forceinline__ void ldm_x4(uint32_t* r, uint32_t addr) {
    asm volatile("ldmatrix.sync.aligned.m8n8.x4.shared.b16 {%0,%1,%2,%3}, [%4];"
                 : "=r"(r[0]), "=r"(r[1]), "=r"(r[2]), "=r"(r[3]) : "r"(addr));
}

__device__ __forceinline__ void ldm_x4_trans(uint32_t* r, uint32_t addr) {
    asm volatile("ldmatrix.sync.aligned.m8n8.x4.trans.shared.b16 {%0,%1,%2,%3}, [%4];"
                 : "=r"(r[0]), "=r"(r[1]), "=r"(r[2]), "=r"(r[3]) : "r"(addr));
}

// D += A(16x16) * B(16x8)  bf16 inputs, fp32 accum
__device__ __forceinline__ void mma16816(float* d, const uint32_t* a, const uint32_t* b) {
    asm volatile(
        "mma.sync.aligned.m16n8k16.row.col.f32.bf16.bf16.f32 "
        "{%0,%1,%2,%3}, {%4,%5,%6,%7}, {%8,%9}, {%0,%1,%2,%3};"
        : "+f"(d[0]), "+f"(d[1]), "+f"(d[2]), "+f"(d[3])
        : "r"(a[0]), "r"(a[1]), "r"(a[2]), "r"(a[3]), "r"(b[0]), "r"(b[1]));
}

__device__ __forceinline__ void cpa16(uint32_t dst, const void* src) {
    asm volatile("cp.async.ca.shared.global [%0], [%1], 16;"
                 :: "r"(dst), "l"(src) : "memory");
}
#define CP_COMMIT() asm volatile("cp.async.commit_group;" ::: "memory")
#define CP_WAIT0()  asm volatile("cp.async.wait_group 0;" ::: "memory")

// 4 fp32 -> 4 bf16 hi + 4 bf16 lo (residual) as packed pairs
__device__ __forceinline__ void split4(float4 v, uint32_t& h01, uint32_t& h23,
                                       uint32_t& l01, uint32_t& l23) {
    asm("cvt.rn.bf16x2.f32 %0, %1, %2;" : "=r"(h01) : "f"(v.y), "f"(v.x));
    asm("cvt.rn.bf16x2.f32 %0, %1, %2;" : "=r"(h23) : "f"(v.w), "f"(v.z));
    float r0 = v.x - __uint_as_float(h01 << 16);
    float r1 = v.y - __uint_as_float(h01 & 0xFFFF0000u);
    float r2 = v.z - __uint_as_float(h23 << 16);
    float r3 = v.w - __uint_as_float(h23 & 0xFFFF0000u);
    asm("cvt.rn.bf16x2.f32 %0, %1, %2;" : "=r"(l01) : "f"(r1), "f"(r0));
    asm("cvt.rn.bf16x2.f32 %0, %1, %2;" : "=r"(l23) : "f"(r3), "f"(r2));
}

// Pack two fp32 -> bf16x2 (lo half = first arg) + residual pair
__device__ __forceinline__ void pack_split(float p0, float p1, uint32_t& h, uint32_t& l) {
    asm("cvt.rn.bf16x2.f32 %0, %1, %2;" : "=r"(h) : "f"(p1), "f"(p0));
    float r0 = p0 - __uint_as_float(h << 16);
    float r1 = p1 - __uint_as_float(h & 0xFFFF0000u);
    asm("cvt.rn.bf16x2.f32 %0, %1, %2;" : "=r"(l) : "f"(r1), "f"(r0));
}

// ============================================================================
// Prepass: elementwise conversions, ONE launch; blockIdx.y selects the tensor
// (0:x 1:y 2:Wq 3:Wk 4:Wv 5:Wo -> hi/lo split; 6:mask -> bf16 bias).
// ============================================================================
#define NX4 (M_TOTAL * D_MODEL / 4)     // 1048576
#define NW4 (D_MODEL * D_MODEL / 4)     // 262144
#define NM4 (BATCH * SEQ * SEQ / 4)     // 2097152

__global__ __launch_bounds__(256) void split_all(
    const float* __restrict__ x,  const float* __restrict__ y,
    const float* __restrict__ wq, const float* __restrict__ wk,
    const float* __restrict__ wv, const float* __restrict__ wo,
    const float* __restrict__ mask)
{
    const int t = blockIdx.y;
    int i = blockIdx.x * 256 + threadIdx.x;

    if (t == 6) {
        if (i >= NM4) return;
        float4 v = ((const float4*)mask)[i];
        float b0 = (v.x - 1.0f) * 1e9f;
        float b1 = (v.y - 1.0f) * 1e9f;
        float b2 = (v.z - 1.0f) * 1e9f;
        float b3 = (v.w - 1.0f) * 1e9f;
        uint32_t h01, h23;
        asm("cvt.rn.bf16x2.f32 %0, %1, %2;" : "=r"(h01) : "f"(b1), "f"(b0));
        asm("cvt.rn.bf16x2.f32 %0, %1, %2;" : "=r"(h23) : "f"(b3), "f"(b2));
        ((uint2*)g_mb)[i] = make_uint2(h01, h23);
        return;
    }

    const float* src;
    __nv_bfloat16 *hi, *lo;
    int n4;
    switch (t) {
        case 0:  src = x;  hi = g_xh;  lo = g_xl;  n4 = NX4; break;
        case 1:  src = y;  hi = g_yh;  lo = g_yl;  n4 = NX4; break;
        case 2:  src = wq; hi = g_wqh; lo = g_wql; n4 = NW4; break;
        case 3:  src = wk; hi = g_wkh; lo = g_wkl; n4 = NW4; break;
        case 4:  src = wv; hi = g_wvh; lo = g_wvl; n4 = NW4; break;
        default: src = wo; hi = g_woh; lo = g_wol; n4 = NW4; break;
    }
    if (i >= n4) return;
    float4 v = ((const float4*)src)[i];
    uint32_t h01, h23, l01, l23;
    split4(v, h01, h23, l01, l23);
    ((uint2*)hi)[i] = make_uint2(h01, h23);
    ((uint2*)lo)[i] = make_uint2(l01, l23);
}

// ============================================================================
// GEMM body [validated R13]: C[M,N] = A[M,K] @ W[N,K]^T + bias
// CTA 128x128, BK=32, 8 warps (warp tile 32x64), cp.async double-buffered,
// 1 barrier per k-iter, 3-pass hi/lo MMA. 2 CTAs/SM.
// ============================================================================
#define BM 128
#define BN 128
#define BK 32
#define KITERS (D_MODEL / BK)       // 32
#define LDTB 80                      // tile row stride bytes (40 halves)
#define GT_AH 0
#define GT_AL 10240
#define GT_BH 20480
#define GT_BL 30720
#define GBUF  40960
#define GEMM_SMEM (2 * GBUF)         // 81920

template<bool SPLIT>
__device__ __forceinline__ void gemm_body(
    const __nv_bfloat16* __restrict__ Ahi, const __nv_bfloat16* __restrict__ Alo,
    const __nv_bfloat16* __restrict__ Whi, const __nv_bfloat16* __restrict__ Wlo,
    const float* __restrict__ bias,
    float* __restrict__ C,
    __nv_bfloat16* __restrict__ Chi,
    __nv_bfloat16* __restrict__ Clo,
    uint32_t smb)
{
    const int tid    = threadIdx.x;
    const int lane   = tid & 31;
    const int wid    = tid >> 5;
    const int warp_m = wid & 3;
    const int warp_n = wid >> 2;
    const int bm     = blockIdx.y;
    const int bn     = blockIdx.x;

    const __nv_bfloat16* Ah = Ahi + (size_t)bm * BM * D_MODEL;
    const __nv_bfloat16* Al = Alo + (size_t)bm * BM * D_MODEL;
    const __nv_bfloat16* Wh = Whi + (size_t)bn * BN * D_MODEL;
    const __nv_bfloat16* Wl = Wlo + (size_t)bn * BN * D_MODEL;

    // Staging map: f = tid + i*256 (0..511); row = f>>2, 16B-chunk = f&3
    uint32_t so[2];
    size_t   go[2];
    #pragma unroll
    for (int i = 0; i < 2; i++) {
        int f = tid + i * 256;
        int r = f >> 2, c = f & 3;
        so[i] = (uint32_t)(r * LDTB + c * 16);
        go[i] = (size_t)r * D_MODEL + c * 8;
    }

    // ldmatrix per-thread byte offsets (within a tile) — validated R5 layout
    const uint32_t a_off =
        (uint32_t)((warp_m * 32 + (lane & 7) + ((lane >> 3) & 1) * 8) * LDTB
                   + (lane >> 4) * 16);
    const uint32_t b_off =
        (uint32_t)((warp_n * 64 + (lane & 7)) * LDTB + (lane >> 3) * 16);

    float acc[2][8][4];
    #pragma unroll
    for (int mt = 0; mt < 2; mt++)
        #pragma unroll
        for (int nt = 0; nt < 8; nt++)
            #pragma unroll
            for (int j = 0; j < 4; j++) acc[mt][nt][j] = 0.0f;

    // Stage k-tile 0 into buffer 0
    #pragma unroll
    for (int i = 0; i < 2; i++) {
        cpa16(smb + GT_AH + so[i], Ah + go[i]);
        cpa16(smb + GT_AL + so[i], Al + go[i]);
        cpa16(smb + GT_BH + so[i], Wh + go[i]);
        cpa16(smb + GT_BL + so[i], Wl + go[i]);
    }
    CP_COMMIT();

    for (int it = 0; it < KITERS; it++) {
        CP_WAIT0();
        __syncthreads();
        if (it + 1 < KITERS) {
            const uint32_t nb = smb + ((it + 1) & 1) * GBUF;
            const size_t g = (size_t)(it + 1) * BK;
            #pragma unroll
            for (int i = 0; i < 2; i++) {
                cpa16(nb + GT_AH + so[i], Ah + go[i] + g);
                cpa16(nb + GT_AL + so[i], Al + go[i] + g);
                cpa16(nb + GT_BH + so[i], Wh + go[i] + g);
                cpa16(nb + GT_BL + so[i], Wl + go[i] + g);
            }
            CP_COMMIT();
        }
        const uint32_t bufb = smb + (it & 1) * GBUF;

        uint32_t ah[2][2][4], al[2][2][4];
        #pragma unroll
        for (int ks = 0; ks < 2; ks++)
            #pragma unroll
            for (int mt = 0; mt < 2; mt++) {
                uint32_t off = a_off + (uint32_t)(mt * 16 * LDTB + ks * 32);
                ldm_x4(ah[ks][mt], bufb + GT_AH + off);
                ldm_x4(al[ks][mt], bufb + GT_AL + off);
            }

        #pragma unroll
        for (int nt = 0; nt < 8; nt++) {
            uint32_t off = b_off + (uint32_t)(nt * 8 * LDTB);
            uint32_t bh[4], bl[4];
            ldm_x4(bh, bufb + GT_BH + off);
            ldm_x4(bl, bufb + GT_BL + off);
            #pragma unroll
            for (int ks = 0; ks < 2; ks++)
                #pragma unroll
                for (int mt = 0; mt < 2; mt++) {
                    mma16816(acc[mt][nt], ah[ks][mt], bh + ks * 2);
                    mma16816(acc[mt][nt], ah[ks][mt], bl + ks * 2);
                    mma16816(acc[mt][nt], al[ks][mt], bh + ks * 2);
                }
        }
    }

    const int lrow = lane >> 2;
    const int lcol = (lane & 3) * 2;
    #pragma unroll
    for (int mt = 0; mt < 2; mt++) {
        const int r0 = bm * BM + warp_m * 32 + mt * 16 + lrow;
        #pragma unroll
        for (int nt = 0; nt < 8; nt++) {
            const int cg = bn * BN + warp_n * 64 + nt * 8 + lcol;
            const float b0 = bias[cg], b1 = bias[cg + 1];
            float c00 = acc[mt][nt][0] + b0, c01 = acc[mt][nt][1] + b1;
            float c10 = acc[mt][nt][2] + b0, c11 = acc[mt][nt][3] + b1;
            if (SPLIT) {
                uint32_t h0, l0, h1, l1;
                pack_split(c00, c01, h0, l0);
                pack_split(c10, c11, h1, l1);
                *(uint32_t*)(Chi + (size_t)r0 * D_MODEL + cg)       = h0;
                *(uint32_t*)(Clo + (size_t)r0 * D_MODEL + cg)       = l0;
                *(uint32_t*)(Chi + (size_t)(r0 + 8) * D_MODEL + cg) = h1;
                *(uint32_t*)(Clo + (size_t)(r0 + 8) * D_MODEL + cg) = l1;
            } else {
                *(float2*)(C + (size_t)r0 * D_MODEL + cg)       = make_float2(c00, c01);
                *(float2*)(C + (size_t)(r0 + 8) * D_MODEL + cg) = make_float2(c10, c11);
            }
        }
    }
}

// Fused Q/K/V projection: blockIdx.z selects which GEMM this CTA computes.
__global__ void __launch_bounds__(256, 2) gemm_qkv(
    const float* __restrict__ bq,
    const float* __restrict__ bk,
    const float* __restrict__ bv)
{
    extern __shared__ char sm[];
    const uint32_t smb = smem_u32(sm);
    const int z = blockIdx.z;
    if (z == 0) {
        gemm_body<true>(g_xh, g_xl, g_wqh, g_wql, bq, nullptr, g_qh, g_ql, smb);
    } else if (z == 1) {
        gemm_body<true>(g_yh, g_yl, g_wkh, g_wkl, bk, nullptr, g_kh, g_kl, smb);
    } else {
        gemm_body<true>(g_yh, g_yl, g_wvh, g_wvl, bv, nullptr, g_vh, g_vl, smb);
    }
}

// Output projection: attn (pre-split) @ Wo^T + bo -> fp32 out
__global__ void __launch_bounds__(256, 2) gemm_o(
    const float* __restrict__ bo, float* __restrict__ out)
{
    extern __shared__ char sm[];
    const uint32_t smb = smem_u32(sm);
    gemm_body<false>(g_ah, g_al, g_woh, g_wol, bo, out, nullptr, nullptr, smb);
}

// ============================================================================
// Flash attention on tensor cores. Inputs pre-split bf16 hi/lo; mask bias
// pre-converted to bf16; output written pre-split for the O-projection.
// ============================================================================
#define LDB     144                  // smem row stride bytes (72 halves)
#define KV_KH   0
#define KV_KL   9216
#define KV_VH   18432
#define KV_VL   27648
#define KVBUF   36864                // per-buffer size
#define OFF_QH  KVBUF                // Q staged in buffer 1, recycled after hoist
#define OFF_QL  (KVBUF + 18432)
#define ATT_SMEM (2 * KVBUF)         // 73728

__device__ __forceinline__ void stage_kv_tile(
    uint32_t bufb,
    const __nv_bfloat16* kh, const __nv_bfloat16* kl,
    const __nv_bfloat16* vh, const __nv_bfloat16* vl,
    int tid)
{
    #pragma unroll
    for (int i = 0; i < 2; i++) {
        int f = tid + i * 256;
        int r = f >> 3, c = f & 7;
        uint32_t so = (uint32_t)(r * LDB + c * 16);
        size_t go = (size_t)r * D_MODEL + c * 8;
        cpa16(bufb + KV_KH + so, kh + go);
        cpa16(bufb + KV_KL + so, kl + go);
        cpa16(bufb + KV_VH + so, vh + go);
        cpa16(bufb + KV_VL + so, vl + go);
    }
}

__global__ void __launch_bounds__(256, 2) flash_attn_mma()
{
    extern __shared__ char sm[];
    const uint32_t smb = smem_u32(sm);
    const int tid  = threadIdx.x;
    const int lane = tid & 31;
    const int wid  = tid >> 5;
    const int bh   = blockIdx.x;
    const int b    = bh >> 4;            // / HEADS
    const int h    = bh & 15;
    const int q0   = blockIdx.y * 128;

    const size_t qrow0 = (size_t)(b * SEQ + q0);
    const size_t krow0 = (size_t)b * SEQ;
    const __nv_bfloat16* Qh = g_qh + qrow0 * D_MODEL + h * HEAD_DIM;
    const __nv_bfloat16* Ql = g_ql + qrow0 * D_MODEL + h * HEAD_DIM;
    const __nv_bfloat16* Kh = g_kh + krow0 * D_MODEL + h * HEAD_DIM;
    const __nv_bfloat16* Kl = g_kl + krow0 * D_MODEL + h * HEAD_DIM;
    const __nv_bfloat16* Vh = g_vh + krow0 * D_MODEL + h * HEAD_DIM;
    const __nv_bfloat16* Vl = g_vl + krow0 * D_MODEL + h * HEAD_DIM;
    const __nv_bfloat16* Mg = g_mb + qrow0 * SEQ;

    // Stage Q (into buffer-1 region) + KV tile 0 (buffer 0)
    #pragma unroll
    for (int i = 0; i < 4; i++) {
        int f = tid + i * 256;
        int r = f >> 3, c = f & 7;
        uint32_t so = (uint32_t)(r * LDB + c * 16);
        size_t go = (size_t)r * D_MODEL + c * 8;
        cpa16(smb + OFF_QH + so, Qh + go);
        cpa16(smb + OFF_QL + so, Ql + go);
    }
    stage_kv_tile(smb, Kh, Kl, Vh, Vl, tid);
    CP_COMMIT();
    CP_WAIT0();
    __syncthreads();

    // Hoist Q fragments to registers (whole KV loop)
    const int qr = wid * 16;
    uint32_t ah[4][4], al[4][4];
    {
        uint32_t base = smb + (uint32_t)((qr + (lane & 15)) * LDB + (lane >> 4) * 16);
        #pragma unroll
        for (int ks = 0; ks < 4; ks++) {
            ldm_x4(ah[ks], base + OFF_QH + ks * 32);
            ldm_x4(al[ks], base + OFF_QL + ks * 32);
        }
    }
    __syncthreads();   // everyone done reading Q smem; buffer 1 is now free

    // Prefetch KV tile 1 into buffer 1 (recycled Q region)
    stage_kv_tile(smb + KVBUF, Kh + 64 * D_MODEL, Kl + 64 * D_MODEL,
                  Vh + 64 * D_MODEL, Vl + 64 * D_MODEL, tid);
    CP_COMMIT();

    const int lrow = lane >> 2;
    const int lcol = (lane & 3) * 2;
    const uint32_t kfrag = (uint32_t)((lane & 7) * LDB + (lane >> 3) * 16);

    float o[8][4];
    #pragma unroll
    for (int dt = 0; dt < 8; dt++)
        #pragma unroll
        for (int j = 0; j < 4; j++) o[dt][j] = 0.0f;
    float m0 = -1e30f, m8 = -1e30f, l0 = 0.0f, l8 = 0.0f;

    for (int kb = 0; kb < SEQ / 64; kb++) {
        if (kb > 0) {
            CP_WAIT0();
            __syncthreads();
        }
        if (kb >= 1 && kb + 1 < SEQ / 64) {
            size_t off = (size_t)(kb + 1) * 64 * D_MODEL;
            stage_kv_tile(smb + ((kb + 1) & 1) * KVBUF,
                          Kh + off, Kl + off, Vh + off, Vl + off, tid);
            CP_COMMIT();
        }
        const uint32_t bufb = smb + (kb & 1) * KVBUF;

        // S = Q K^T (3-pass hi/lo), warp tile 16x64
        float s[8][4];
        #pragma unroll
        for (int nt = 0; nt < 8; nt++)
            #pragma unroll
            for (int j = 0; j < 4; j++) s[nt][j] = 0.0f;

        #pragma unroll
        for (int nt = 0; nt < 8; nt++) {
            uint32_t ka = bufb + kfrag + (uint32_t)(nt * 8 * LDB);
            uint32_t kh[8], kl[8];
            ldm_x4(kh,     ka + KV_KH);
            ldm_x4(kh + 4, ka + KV_KH + 64);
            ldm_x4(kl,     ka + KV_KL);
            ldm_x4(kl + 4, ka + KV_KL + 64);
            #pragma unroll
            for (int ks = 0; ks < 4; ks++) {
                mma16816(s[nt], ah[ks], kh + ks * 2);
                mma16816(s[nt], ah[ks], kl + ks * 2);
                mma16816(s[nt], al[ks], kh + ks * 2);
            }
        }

        // Scale + mask-bias (bf16) + row max
        const __nv_bfloat16* mrow = Mg + (size_t)kb * 64;
        float tmax0 = -1e30f, tmax8 = -1e30f;
        #pragma unroll
        for (int nt = 0; nt < 8; nt++) {
            int c = nt * 8 + lcol;
            float2 mk0 = __bfloat1622float2(
                *(const __nv_bfloat162*)(mrow + (size_t)(qr + lrow) * SEQ + c));
            float2 mk8 = __bfloat1622float2(
                *(const __nv_bfloat162*)(mrow + (size_t)(qr + lrow + 8) * SEQ + c));
            s[nt][0] = fmaf(s[nt][0], 0.125f, mk0.x);
            s[nt][1] = fmaf(s[nt][1], 0.125f, mk0.y);
            s[nt][2] = fmaf(s[nt][2], 0.125f, mk8.x);
            s[nt][3] = fmaf(s[nt][3], 0.125f, mk8.y);
            tmax0 = fmaxf(tmax0, fmaxf(s[nt][0], s[nt][1]));
            tmax8 = fmaxf(tmax8, fmaxf(s[nt][2], s[nt][3]));
        }
        tmax0 = fmaxf(tmax0, __shfl_xor_sync(0xffffffffu, tmax0, 1));
        tmax0 = fmaxf(tmax0, __shfl_xor_sync(0xffffffffu, tmax0, 2));
        tmax8 = fmaxf(tmax8, __shfl_xor_sync(0xffffffffu, tmax8, 1));
        tmax8 = fmaxf(tmax8, __shfl_xor_sync(0xffffffffu, tmax8, 2));

        float mn0 = fmaxf(m0, tmax0), mn8 = fmaxf(m8, tmax8);
        float al0 = __expf(m0 - mn0), al8 = __expf(m8 - mn8);
        m0 = mn0; m8 = mn8;

        // exp, sums, and P fragments (hi/lo) in registers
        float sum0 = 0.0f, sum8 = 0.0f;
        uint32_t pah[4][4], pal[4][4];
        #pragma unroll
        for (int nt = 0; nt < 8; nt++) {
            float p0 = __expf(s[nt][0] - mn0);
            float p1 = __expf(s[nt][1] - mn0);
            float p2 = __expf(s[nt][2] - mn8);
            float p3 = __expf(s[nt][3] - mn8);
            sum0 += p0 + p1;
            sum8 += p2 + p3;
            int ks = nt >> 1, slot = (nt & 1) * 2;
            pack_split(p0, p1, pah[ks][slot],     pal[ks][slot]);
            pack_split(p2, p3, pah[ks][slot + 1], pal[ks][slot + 1]);
        }
        sum0 += __shfl_xor_sync(0xffffffffu, sum0, 1);
        sum0 += __shfl_xor_sync(0xffffffffu, sum0, 2);
        sum8 += __shfl_xor_sync(0xffffffffu, sum8, 1);
        sum8 += __shfl_xor_sync(0xffffffffu, sum8, 2);
        l0 = l0 * al0 + sum0;
        l8 = l8 * al8 + sum8;

        // Rescale O, then O += P @ V (3-pass hi/lo, V via ldmatrix.trans)
        #pragma unroll
        for (int dt = 0; dt < 8; dt++) {
            o[dt][0] *= al0; o[dt][1] *= al0;
            o[dt][2] *= al8; o[dt][3] *= al8;
        }
        #pragma unroll
        for (int dt = 0; dt < 8; dt++) {
            uint32_t va = bufb + (uint32_t)(lane * LDB + dt * 16);
            uint32_t vh[8], vl[8];
            ldm_x4_trans(vh,     va + KV_VH);
            ldm_x4_trans(vh + 4, va + KV_VH + 32 * LDB);
            ldm_x4_trans(vl,     va + KV_VL);
            ldm_x4_trans(vl + 4, va + KV_VL + 32 * LDB);
            #pragma unroll
            for (int ks = 0; ks < 4; ks++) {
                mma16816(o[dt], pah[ks], vh + ks * 2);
                mma16816(o[dt], pah[ks], vl + ks * 2);
                mma16816(o[dt], pal[ks], vh + ks * 2);
            }
        }
    }

    // Normalize and store pre-split (hi/lo) for the O-projection
    const float inv0 = 1.0f / l0;
    const float inv8 = 1.0f / l8;
    const size_t orow = (qrow0 + qr + lrow) * D_MODEL + h * HEAD_DIM;
    #pragma unroll
    for (int dt = 0; dt < 8; dt++) {
        int c = dt * 8 + lcol;
        uint32_t h0, l0r, h1, l1r;
        pack_split(o[dt][0] * inv0, o[dt][1] * inv0, h0, l0r);
        pack_split(o[dt][2] * inv8, o[dt][3] * inv8, h1, l1r);
        *(uint32_t*)(g_ah + orow + c)               = h0;
        *(uint32_t*)(g_al + orow + c)               = l0r;
        *(uint32_t*)(g_ah + orow + 8 * D_MODEL + c) = h1;
        *(uint32_t*)(g_al + orow + 8 * D_MODEL + c) = l1r;
    }
}

// ----------------------------------------------------------------------------
extern "C" void kernel_launch(void* const* d_in, const int* in_sizes, int n_in,
                              void* d_out, int out_size)
{
    const float* x    = (const float*)d_in[0];
    const float* y    = (const float*)d_in[1];
    const float* mask = (const float*)d_in[2];
    const float* Wq   = (const float*)d_in[3];
    const float* bq   = (const float*)d_in[4];
    const float* Wk   = (const float*)d_in[5];
    const float* bk   = (const float*)d_in[6];
    const float* Wv   = (const float*)d_in[7];
    const float* bv   = (const float*)d_in[8];
    const float* Wo   = (const float*)d_in[9];
    const float* bo   = (const float*)d_in[10];
    float* out = (float*)d_out;

    cudaFuncSetAttribute(gemm_qkv,
                         cudaFuncAttributeMaxDynamicSharedMemorySize, GEMM_SMEM);
    cudaFuncSetAttribute(gemm_o,
                         cudaFuncAttributeMaxDynamicSharedMemorySize, GEMM_SMEM);
    cudaFuncSetAttribute(flash_attn_mma,
                         cudaFuncAttributeMaxDynamicSharedMemorySize, ATT_SMEM);

    // Prepass: split x/y/W* and convert mask to bf16 bias (one launch)
    dim3 sgrid(NM4 / 256, 7);
    split_all<<<sgrid, 256>>>(x, y, Wq, Wk, Wv, Wo, mask);

    // Fused Q/K/V projections (one launch, 768 CTAs)
    dim3 ggrid(D_MODEL / BN, M_TOTAL / BM, 3);   // (8, 32, 3)
    gemm_qkv<<<ggrid, 256, GEMM_SMEM>>>(bq, bk, bv);

    // Attention
    dim3 agrid(BATCH * HEADS, SEQ / 128);        // (32, 16)
    flash_attn_mma<<<agrid, 256, ATT_SMEM>>>();

    // Output projection
    dim3 ogrid(D_MODEL / BN, M_TOTAL / BM);      // (8, 32)
    gemm_o<<<ogrid, 256, GEMM_SMEM>>>(bo, out);
}

// round 17
// speedup vs baseline: 1.4596x; 1.3681x over previous
#include <cuda_runtime.h>
#include <cuda_fp16.h>
#include <cuda_bf16.h>
#include <cstdint>
#include <math.h>

// Problem constants (fixed by the dataset)
#define D_MODEL   1024
#define HEADS     16
#define HEAD_DIM  64
#define BATCH     2
#define SEQ       2048
#define M_TOTAL   (BATCH * SEQ)       // 4096 rows for projection GEMMs

// Scratch: device globals (no allocations allowed).
// Activations are fp16 hi/lo split pairs (hi + lo ~= fp32, err ~2^-22).
// Weights / K / V are single fp16 (err 2^-11; 2-pass MMA keeps total ~2e-4).
__device__ __half g_xh[M_TOTAL * D_MODEL];
__device__ __half g_xl[M_TOTAL * D_MODEL];
__device__ __half g_yh[M_TOTAL * D_MODEL];
__device__ __half g_yl[M_TOTAL * D_MODEL];
__device__ __half g_wqh[D_MODEL * D_MODEL];
__device__ __half g_wkh[D_MODEL * D_MODEL];
__device__ __half g_wvh[D_MODEL * D_MODEL];
__device__ __half g_woh[D_MODEL * D_MODEL];
__device__ __half g_qh[M_TOTAL * D_MODEL];
__device__ __half g_ql[M_TOTAL * D_MODEL];
__device__ __half g_kh[M_TOTAL * D_MODEL];   // K: hi only
__device__ __half g_vh[M_TOTAL * D_MODEL];   // V: hi only
__device__ __half g_ah[M_TOTAL * D_MODEL];
__device__ __half g_al[M_TOTAL * D_MODEL];
// Mask bias: (mask - 1) * 1e9, bf16 (fp16 would overflow at -1e9)
__device__ __nv_bfloat16 g_mb[BATCH * SEQ * SEQ];

// ============================================================================
// Warp-level MMA helpers (mma.sync + ldmatrix + cp.async — base sm_103)
// ============================================================================
__device__ __forceinline__ uint32_t smem_u32(const void* p) {
    uint32_t a;
    asm("{ .reg .u64 t; cvta.to.shared.u64 t, %1; cvt.u32.u64 %0, t; }"
        : "=r"(a) : "l"(p));
    return a;
}

__device__ __forceinline__ void ldm_x4(uint32_t* r, uint32_t addr) {
    asm volatile("ldmatrix.sync.aligned.m8n8.x4.shared.b16 {%0,%1,%2,%3}, [%4];"
                 : "=r"(r[0]), "=r"(r[1]), "=r"(r[2]), "=r"(r[3]) : "r"(addr));
}

__device__ __forceinline__ void ldm_x4_trans(uint32_t* r, uint32_t addr) {
    asm volatile("ldmatrix.sync.aligned.m8n8.x4.trans.shared.b16 {%0,%1,%2,%3}, [%4];"
                 : "=r"(r[0]), "=r"(r[1]), "=r"(r[2]), "=r"(r[3]) : "r"(addr));
}

// D += A(16x16) * B(16x8)  fp16 inputs, fp32 accum
__device__ __forceinline__ void mma16816(float* d, const uint32_t* a, const uint32_t* b) {
    asm volatile(
        "mma.sync.aligned.m16n8k16.row.col.f32.f16.f16.f32 "
        "{%0,%1,%2,%3}, {%4,%5,%6,%7}, {%8,%9}, {%0,%1,%2,%3};"
        : "+f"(d[0]), "+f"(d[1]), "+f"(d[2]), "+f"(d[3])
        : "r"(a[0]), "r"(a[1]), "r"(a[2]), "r"(a[3]), "r"(b[0]), "r"(b[1]));
}

__device__ __forceinline__ void cpa16(uint32_t dst, const void* src) {
    asm volatile("cp.async.ca.shared.global [%0], [%1], 16;"
                 :: "r"(dst), "l"(src) : "memory");
}
#define CP_COMMIT() asm volatile("cp.async.commit_group;" ::: "memory")
#define CP_WAIT0()  asm volatile("cp.async.wait_group 0;" ::: "memory")

// 4 fp32 -> 4 fp16 hi + 4 fp16 lo (residual) as packed pairs
__device__ __forceinline__ void split4h(float4 v, uint32_t& h01, uint32_t& h23,
                                        uint32_t& l01, uint32_t& l23) {
    asm("cvt.rn.f16x2.f32 %0, %1, %2;" : "=r"(h01) : "f"(v.y), "f"(v.x));
    asm("cvt.rn.f16x2.f32 %0, %1, %2;" : "=r"(h23) : "f"(v.w), "f"(v.z));
    __half2 p01 = *reinterpret_cast<__half2*>(&h01);
    __half2 p23 = *reinterpret_cast<__half2*>(&h23);
    float r0 = v.x - __low2float(p01);
    float r1 = v.y - __high2float(p01);
    float r2 = v.z - __low2float(p23);
    float r3 = v.w - __high2float(p23);
    asm("cvt.rn.f16x2.f32 %0, %1, %2;" : "=r"(l01) : "f"(r1), "f"(r0));
    asm("cvt.rn.f16x2.f32 %0, %1, %2;" : "=r"(l23) : "f"(r3), "f"(r2));
}

// Pack two fp32 -> fp16x2 (lo half = first arg) + residual pair
__device__ __forceinline__ void pack_split_h(float p0, float p1, uint32_t& h, uint32_t& l) {
    asm("cvt.rn.f16x2.f32 %0, %1, %2;" : "=r"(h) : "f"(p1), "f"(p0));
    __half2 hh = *reinterpret_cast<__half2*>(&h);
    float r0 = p0 - __low2float(hh);
    float r1 = p1 - __high2float(hh);
    asm("cvt.rn.f16x2.f32 %0, %1, %2;" : "=r"(l) : "f"(r1), "f"(r0));
}

// ============================================================================
// Prepass: elementwise conversions, ONE launch; blockIdx.y selects the tensor
// (0:x 1:y -> fp16 hi/lo split; 2:Wq 3:Wk 4:Wv 5:Wo -> fp16 hi only;
//  6:mask -> bf16 bias).
// ============================================================================
#define NX4 (M_TOTAL * D_MODEL / 4)     // 1048576
#define NW4 (D_MODEL * D_MODEL / 4)     // 262144
#define NM4 (BATCH * SEQ * SEQ / 4)     // 2097152

__global__ __launch_bounds__(256) void split_all(
    const float* __restrict__ x,  const float* __restrict__ y,
    const float* __restrict__ wq, const float* __restrict__ wk,
    const float* __restrict__ wv, const float* __restrict__ wo,
    const float* __restrict__ mask)
{
    const int t = blockIdx.y;
    int i = blockIdx.x * 256 + threadIdx.x;

    if (t == 6) {
        if (i >= NM4) return;
        float4 v = ((const float4*)mask)[i];
        float b0 = (v.x - 1.0f) * 1e9f;
        float b1 = (v.y - 1.0f) * 1e9f;
        float b2 = (v.z - 1.0f) * 1e9f;
        float b3 = (v.w - 1.0f) * 1e9f;
        uint32_t h01, h23;
        asm("cvt.rn.bf16x2.f32 %0, %1, %2;" : "=r"(h01) : "f"(b1), "f"(b0));
        asm("cvt.rn.bf16x2.f32 %0, %1, %2;" : "=r"(h23) : "f"(b3), "f"(b2));
        ((uint2*)g_mb)[i] = make_uint2(h01, h23);
        return;
    }

    if (t <= 1) {                     // activations: hi/lo split
        if (i >= NX4) return;
        const float* src = t ? y : x;
        __half* hi = t ? g_yh : g_xh;
        __half* lo = t ? g_yl : g_xl;
        float4 v = ((const float4*)src)[i];
        uint32_t h01, h23, l01, l23;
        split4h(v, h01, h23, l01, l23);
        ((uint2*)hi)[i] = make_uint2(h01, h23);
        ((uint2*)lo)[i] = make_uint2(l01, l23);
        return;
    }

    // weights: hi only
    if (i >= NW4) return;
    const float* src;
    __half* hi;
    switch (t) {
        case 2:  src = wq; hi = g_wqh; break;
        case 3:  src = wk; hi = g_wkh; break;
        case 4:  src = wv; hi = g_wvh; break;
        default: src = wo; hi = g_woh; break;
    }
    float4 v = ((const float4*)src)[i];
    uint32_t h01, h23;
    asm("cvt.rn.f16x2.f32 %0, %1, %2;" : "=r"(h01) : "f"(v.y), "f"(v.x));
    asm("cvt.rn.f16x2.f32 %0, %1, %2;" : "=r"(h23) : "f"(v.w), "f"(v.z));
    ((uint2*)hi)[i] = make_uint2(h01, h23);
}

// ============================================================================
// GEMM body: C[M,N] = A[M,K] @ W[N,K]^T + bias   (M=4096, N=K=1024)
// A pre-split fp16 hi/lo, W single fp16. CTA 128x128, BK=32, 8 warps
// (warp tile 32x64), cp.async double-buffered, 1 barrier/iter, 2-pass MMA.
// ============================================================================
#define BM 128
#define BN 128
#define BK 32
#define KITERS (D_MODEL / BK)       // 32
#define LDTB 80                      // tile row stride bytes (40 halves)
#define GT_AH 0
#define GT_AL 10240
#define GT_BH 20480
#define GBUF  30720
#define GEMM_SMEM (2 * GBUF)         // 61440

template<bool SPLIT>
__device__ __forceinline__ void gemm_body(
    const __half* __restrict__ Ahi, const __half* __restrict__ Alo,
    const __half* __restrict__ Whi,
    const float* __restrict__ bias,
    float* __restrict__ C,
    __half* __restrict__ Chi,
    __half* __restrict__ Clo,
    uint32_t smb)
{
    const int tid    = threadIdx.x;
    const int lane   = tid & 31;
    const int wid    = tid >> 5;
    const int warp_m = wid & 3;
    const int warp_n = wid >> 2;
    const int bm     = blockIdx.y;
    const int bn     = blockIdx.x;

    const __half* Ah = Ahi + (size_t)bm * BM * D_MODEL;
    const __half* Al = Alo + (size_t)bm * BM * D_MODEL;
    const __half* Wh = Whi + (size_t)bn * BN * D_MODEL;

    // Staging map: f = tid + i*256 (0..511); row = f>>2, 16B-chunk = f&3
    uint32_t so[2];
    size_t   go[2];
    #pragma unroll
    for (int i = 0; i < 2; i++) {
        int f = tid + i * 256;
        int r = f >> 2, c = f & 3;
        so[i] = (uint32_t)(r * LDTB + c * 16);
        go[i] = (size_t)r * D_MODEL + c * 8;
    }

    // ldmatrix per-thread byte offsets (within a tile) — validated R5 layout
    const uint32_t a_off =
        (uint32_t)((warp_m * 32 + (lane & 7) + ((lane >> 3) & 1) * 8) * LDTB
                   + (lane >> 4) * 16);
    const uint32_t b_off =
        (uint32_t)((warp_n * 64 + (lane & 7)) * LDTB + (lane >> 3) * 16);

    float acc[2][8][4];
    #pragma unroll
    for (int mt = 0; mt < 2; mt++)
        #pragma unroll
        for (int nt = 0; nt < 8; nt++)
            #pragma unroll
            for (int j = 0; j < 4; j++) acc[mt][nt][j] = 0.0f;

    // Stage k-tile 0 into buffer 0
    #pragma unroll
    for (int i = 0; i < 2; i++) {
        cpa16(smb + GT_AH + so[i], Ah + go[i]);
        cpa16(smb + GT_AL + so[i], Al + go[i]);
        cpa16(smb + GT_BH + so[i], Wh + go[i]);
    }
    CP_COMMIT();

    for (int it = 0; it < KITERS; it++) {
        CP_WAIT0();
        __syncthreads();
        if (it + 1 < KITERS) {
            const uint32_t nb = smb + ((it + 1) & 1) * GBUF;
            const size_t g = (size_t)(it + 1) * BK;
            #pragma unroll
            for (int i = 0; i < 2; i++) {
                cpa16(nb + GT_AH + so[i], Ah + go[i] + g);
                cpa16(nb + GT_AL + so[i], Al + go[i] + g);
                cpa16(nb + GT_BH + so[i], Wh + go[i] + g);
            }
            CP_COMMIT();
        }
        const uint32_t bufb = smb + (it & 1) * GBUF;

        uint32_t ah[2][2][4], al[2][2][4];
        #pragma unroll
        for (int ks = 0; ks < 2; ks++)
            #pragma unroll
            for (int mt = 0; mt < 2; mt++) {
                uint32_t off = a_off + (uint32_t)(mt * 16 * LDTB + ks * 32);
                ldm_x4(ah[ks][mt], bufb + GT_AH + off);
                ldm_x4(al[ks][mt], bufb + GT_AL + off);
            }

        #pragma unroll
        for (int nt = 0; nt < 8; nt++) {
            uint32_t off = b_off + (uint32_t)(nt * 8 * LDTB);
            uint32_t bh[4];
            ldm_x4(bh, bufb + GT_BH + off);
            #pragma unroll
            for (int ks = 0; ks < 2; ks++)
                #pragma unroll
                for (int mt = 0; mt < 2; mt++) {
                    mma16816(acc[mt][nt], ah[ks][mt], bh + ks * 2);
                    mma16816(acc[mt][nt], al[ks][mt], bh + ks * 2);
                }
        }
    }

    const int lrow = lane >> 2;
    const int lcol = (lane & 3) * 2;
    #pragma unroll
    for (int mt = 0; mt < 2; mt++) {
        const int r0 = bm * BM + warp_m * 32 + mt * 16 + lrow;
        #pragma unroll
        for (int nt = 0; nt < 8; nt++) {
            const int cg = bn * BN + warp_n * 64 + nt * 8 + lcol;
            const float b0 = bias[cg], b1 = bias[cg + 1];
            float c00 = acc[mt][nt][0] + b0, c01 = acc[mt][nt][1] + b1;
            float c10 = acc[mt][nt][2] + b0, c11 = acc[mt][nt][3] + b1;
            if (SPLIT) {
                uint32_t h0, l0, h1, l1;
                pack_split_h(c00, c01, h0, l0);
                pack_split_h(c10, c11, h1, l1);
                *(uint32_t*)(Chi + (size_t)r0 * D_MODEL + cg)       = h0;
                *(uint32_t*)(Clo + (size_t)r0 * D_MODEL + cg)       = l0;
                *(uint32_t*)(Chi + (size_t)(r0 + 8) * D_MODEL + cg) = h1;
                *(uint32_t*)(Clo + (size_t)(r0 + 8) * D_MODEL + cg) = l1;
            } else {
                *(float2*)(C + (size_t)r0 * D_MODEL + cg)       = make_float2(c00, c01);
                *(float2*)(C + (size_t)(r0 + 8) * D_MODEL + cg) = make_float2(c10, c11);
            }
        }
    }
}

// Fused Q/K/V projection: blockIdx.z selects which GEMM this CTA computes.
// Q gets hi/lo split output; K and V get hi-only (lo written but unused is
// avoided: K/V kernels write hi to g_kh/g_vh and lo to a scratch that IS the
// ql buffer? No — K/V use SPLIT=true with their own lo arrays unused).
// Simpler: Q -> (g_qh, g_ql); K -> (g_kh, g_ql_dummy)... we just reuse SPLIT
// and give K/V their hi array plus g_ql as a throwaway lo target is WRONG
// (Q needs g_ql). Instead K/V write lo into g_xl (dead after QKV GEMMs read
// it... but K GEMM itself reads g_yl — hazard). Use dedicated dump:
__device__ __half g_dump[M_TOTAL * D_MODEL];

__global__ void __launch_bounds__(256, 2) gemm_qkv(
    const float* __restrict__ bq,
    const float* __restrict__ bk,
    const float* __restrict__ bv)
{
    extern __shared__ char sm[];
    const uint32_t smb = smem_u32(sm);
    const int z = blockIdx.z;
    if (z == 0) {
        gemm_body<true>(g_xh, g_xl, g_wqh, bq, nullptr, g_qh, g_ql, smb);
    } else if (z == 1) {
        gemm_body<true>(g_yh, g_yl, g_wkh, bk, nullptr, g_kh, g_dump, smb);
    } else {
        gemm_body<true>(g_yh, g_yl, g_wvh, bv, nullptr, g_vh, g_dump, smb);
    }
}

// Output projection: attn (pre-split) @ Wo^T + bo -> fp32 out
__global__ void __launch_bounds__(256, 2) gemm_o(
    const float* __restrict__ bo, float* __restrict__ out)
{
    extern __shared__ char sm[];
    const uint32_t smb = smem_u32(sm);
    gemm_body<false>(g_ah, g_al, g_woh, bo, out, nullptr, nullptr, smb);
}

// ============================================================================
// Flash attention on tensor cores. Q pre-split fp16 hi/lo; K/V single fp16;
// mask bias bf16; output written pre-split for the O-projection.
// Block: 128 q-rows x one (b,h). 8 warps, warp owns 16 rows. KV tiles of 64,
// cp.async double-buffered; Q staged across both KV buffers then recycled.
// ============================================================================
#define LDB     144                  // smem row stride bytes (72 halves)
#define KV_KH   0
#define KV_VH   9216
#define KVBUF   18432                // per-buffer size (K + V, hi only)
#define OFF_QH  0                    // Q hi staged in buffer 0 region
#define OFF_QL  KVBUF                // Q lo staged in buffer 1 region
#define ATT_SMEM (2 * KVBUF)         // 36864

__device__ __forceinline__ void stage_kv_tile(
    uint32_t bufb,
    const __half* kh, const __half* vh,
    int tid)
{
    #pragma unroll
    for (int i = 0; i < 2; i++) {
        int f = tid + i * 256;
        int r = f >> 3, c = f & 7;
        uint32_t so = (uint32_t)(r * LDB + c * 16);
        size_t go = (size_t)r * D_MODEL + c * 8;
        cpa16(bufb + KV_KH + so, kh + go);
        cpa16(bufb + KV_VH + so, vh + go);
    }
}

__global__ void __launch_bounds__(256, 2) flash_attn_mma()
{
    extern __shared__ char sm[];
    const uint32_t smb = smem_u32(sm);
    const int tid  = threadIdx.x;
    const int lane = tid & 31;
    const int wid  = tid >> 5;
    const int bh   = blockIdx.x;
    const int b    = bh >> 4;            // / HEADS
    const int h    = bh & 15;
    const int q0   = blockIdx.y * 128;

    const size_t qrow0 = (size_t)(b * SEQ + q0);
    const size_t krow0 = (size_t)b * SEQ;
    const __half* Qh = g_qh + qrow0 * D_MODEL + h * HEAD_DIM;
    const __half* Ql = g_ql + qrow0 * D_MODEL + h * HEAD_DIM;
    const __half* Kh = g_kh + krow0 * D_MODEL + h * HEAD_DIM;
    const __half* Vh = g_vh + krow0 * D_MODEL + h * HEAD_DIM;
    const __nv_bfloat16* Mg = g_mb + qrow0 * SEQ;

    // Stage Q hi/lo across both buffer regions
    #pragma unroll
    for (int i = 0; i < 4; i++) {
        int f = tid + i * 256;
        int r = f >> 3, c = f & 7;
        uint32_t so = (uint32_t)(r * LDB + c * 16);
        size_t go = (size_t)r * D_MODEL + c * 8;
        cpa16(smb + OFF_QH + so, Qh + go);
        cpa16(smb + OFF_QL + so, Ql + go);
    }
    CP_COMMIT();
    CP_WAIT0();
    __syncthreads();

    // Hoist Q fragments to registers (whole KV loop)
    const int qr = wid * 16;
    uint32_t ah[4][4], al[4][4];
    {
        uint32_t base = smb + (uint32_t)((qr + (lane & 15)) * LDB + (lane >> 4) * 16);
        #pragma unroll
        for (int ks = 0; ks < 4; ks++) {
            ldm_x4(ah[ks], base + OFF_QH + ks * 32);
            ldm_x4(al[ks], base + OFF_QL + ks * 32);
        }
    }
    __syncthreads();   // everyone done reading Q smem; both buffers now free

    // Stage KV tile 0 into buffer 0
    stage_kv_tile(smb, Kh, Vh, tid);
    CP_COMMIT();

    const int lrow = lane >> 2;
    const int lcol = (lane & 3) * 2;
    const uint32_t kfrag = (uint32_t)((lane & 7) * LDB + (lane >> 3) * 16);

    float o[8][4];
    #pragma unroll
    for (int dt = 0; dt < 8; dt++)
        #pragma unroll
        for (int j = 0; j < 4; j++) o[dt][j] = 0.0f;
    float m0 = -1e30f, m8 = -1e30f, l0 = 0.0f, l8 = 0.0f;

    for (int kb = 0; kb < SEQ / 64; kb++) {
        CP_WAIT0();
        __syncthreads();
        if (kb + 1 < SEQ / 64) {
            size_t off = (size_t)(kb + 1) * 64 * D_MODEL;
            stage_kv_tile(smb + ((kb + 1) & 1) * KVBUF, Kh + off, Vh + off, tid);
            CP_COMMIT();
        }
        const uint32_t bufb = smb + (kb & 1) * KVBUF;

        // S = Q K^T (2-pass fp16: qh*kh + ql*kh), warp tile 16x64
        float s[8][4];
        #pragma unroll
        for (int nt = 0; nt < 8; nt++)
            #pragma unroll
            for (int j = 0; j < 4; j++) s[nt][j] = 0.0f;

        #pragma unroll
        for (int nt = 0; nt < 8; nt++) {
            uint32_t ka = bufb + kfrag + (uint32_t)(nt * 8 * LDB);
            uint32_t kh[8];
            ldm_x4(kh,     ka + KV_KH);
            ldm_x4(kh + 4, ka + KV_KH + 64);
            #pragma unroll
            for (int ks = 0; ks < 4; ks++) {
                mma16816(s[nt], ah[ks], kh + ks * 2);
                mma16816(s[nt], al[ks], kh + ks * 2);
            }
        }

        // Scale + mask-bias (bf16) + row max
        const __nv_bfloat16* mrow = Mg + (size_t)kb * 64;
        float tmax0 = -1e30f, tmax8 = -1e30f;
        #pragma unroll
        for (int nt = 0; nt < 8; nt++) {
            int c = nt * 8 + lcol;
            float2 mk0 = __bfloat1622float2(
                *(const __nv_bfloat162*)(mrow + (size_t)(qr + lrow) * SEQ + c));
            float2 mk8 = __bfloat1622float2(
                *(const __nv_bfloat162*)(mrow + (size_t)(qr + lrow + 8) * SEQ + c));
            s[nt][0] = fmaf(s[nt][0], 0.125f, mk0.x);
            s[nt][1] = fmaf(s[nt][1], 0.125f, mk0.y);
            s[nt][2] = fmaf(s[nt][2], 0.125f, mk8.x);
            s[nt][3] = fmaf(s[nt][3], 0.125f, mk8.y);
            tmax0 = fmaxf(tmax0, fmaxf(s[nt][0], s[nt][1]));
            tmax8 = fmaxf(tmax8, fmaxf(s[nt][2], s[nt][3]));
        }
        tmax0 = fmaxf(tmax0, __shfl_xor_sync(0xffffffffu, tmax0, 1));
        tmax0 = fmaxf(tmax0, __shfl_xor_sync(0xffffffffu, tmax0, 2));
        tmax8 = fmaxf(tmax8, __shfl_xor_sync(0xffffffffu, tmax8, 1));
        tmax8 = fmaxf(tmax8, __shfl_xor_sync(0xffffffffu, tmax8, 2));

        float mn0 = fmaxf(m0, tmax0), mn8 = fmaxf(m8, tmax8);
        float al0 = __expf(m0 - mn0), al8 = __expf(m8 - mn8);
        m0 = mn0; m8 = mn8;

        // exp, sums, and P fragments (fp16 hi/lo) in registers
        float sum0 = 0.0f, sum8 = 0.0f;
        uint32_t pah[4][4], pal[4][4];
        #pragma unroll
        for (int nt = 0; nt < 8; nt++) {
            float p0 = __expf(s[nt][0] - mn0);
            float p1 = __expf(s[nt][1] - mn0);
            float p2 = __expf(s[nt][2] - mn8);
            float p3 = __expf(s[nt][3] - mn8);
            sum0 += p0 + p1;
            sum8 += p2 + p3;
            int ks = nt >> 1, slot = (nt & 1) * 2;
            pack_split_h(p0, p1, pah[ks][slot],     pal[ks][slot]);
            pack_split_h(p2, p3, pah[ks][slot + 1], pal[ks][slot + 1]);
        }
        sum0 += __shfl_xor_sync(0xffffffffu, sum0, 1);
        sum0 += __shfl_xor_sync(0xffffffffu, sum0, 2);
        sum8 += __shfl_xor_sync(0xffffffffu, sum8, 1);
        sum8 += __shfl_xor_sync(0xffffffffu, sum8, 2);
        l0 = l0 * al0 + sum0;
        l8 = l8 * al8 + sum8;

        // Rescale O, then O += P @ V (2-pass fp16, V via ldmatrix.trans)
        #pragma unroll
        for (int dt = 0; dt < 8; dt++) {
            o[dt][0] *= al0; o[dt][1] *= al0;
            o[dt][2] *= al8; o[dt][3] *= al8;
        }
        #pragma unroll
        for (int dt = 0; dt < 8; dt++) {
            uint32_t va = bufb + KV_VH + (uint32_t)(lane * LDB + dt * 16);
            uint32_t vh[8];
            ldm_x4_trans(vh,     va);
            ldm_x4_trans(vh + 4, va + 32 * LDB);
            #pragma unroll
            for (int ks = 0; ks < 4; ks++) {
                mma16816(o[dt], pah[ks], vh + ks * 2);
                mma16816(o[dt], pal[ks], vh + ks * 2);
            }
        }
    }

    // Normalize and store pre-split (fp16 hi/lo) for the O-projection
    const float inv0 = 1.0f / l0;
    const float inv8 = 1.0f / l8;
    const size_t orow = (qrow0 + qr + lrow) * D_MODEL + h * HEAD_DIM;
    #pragma unroll
    for (int dt = 0; dt < 8; dt++) {
        int c = dt * 8 + lcol;
        uint32_t h0, l0r, h1, l1r;
        pack_split_h(o[dt][0] * inv0, o[dt][1] * inv0, h0, l0r);
        pack_split_h(o[dt][2] * inv8, o[dt][3] * inv8, h1, l1r);
        *(uint32_t*)(g_ah + orow + c)               = h0;
        *(uint32_t*)(g_al + orow + c)               = l0r;
        *(uint32_t*)(g_ah + orow + 8 * D_MODEL + c) = h1;
        *(uint32_t*)(g_al + orow + 8 * D_MODEL + c) = l1r;
    }
}

// ----------------------------------------------------------------------------
extern "C" void kernel_launch(void* const* d_in, const int* in_sizes, int n_in,
                              void* d_out, int out_size)
{
    const float* x    = (const float*)d_in[0];
    const float* y    = (const float*)d_in[1];
    const float* mask = (const float*)d_in[2];
    const float* Wq   = (const float*)d_in[3];
    const float* bq   = (const float*)d_in[4];
    const float* Wk   = (const float*)d_in[5];
    const float* bk   = (const float*)d_in[6];
    const float* Wv   = (const float*)d_in[7];
    const float* bv   = (const float*)d_in[8];
    const float* Wo   = (const float*)d_in[9];
    const float* bo   = (const float*)d_in[10];
    float* out = (float*)d_out;

    cudaFuncSetAttribute(gemm_qkv,
                         cudaFuncAttributeMaxDynamicSharedMemorySize, GEMM_SMEM);
    cudaFuncSetAttribute(gemm_o,
                         cudaFuncAttributeMaxDynamicSharedMemorySize, GEMM_SMEM);
    cudaFuncSetAttribute(flash_attn_mma,
                         cudaFuncAttributeMaxDynamicSharedMemorySize, ATT_SMEM);

    // Prepass: split x/y, convert W* to fp16, mask to bf16 bias (one launch)
    dim3 sgrid(NM4 / 256, 7);
    split_all<<<sgrid, 256>>>(x, y, Wq, Wk, Wv, Wo, mask);

    // Fused Q/K/V projections (one launch, 768 CTAs)
    dim3 ggrid(D_MODEL / BN, M_TOTAL / BM, 3);   // (8, 32, 3)
    gemm_qkv<<<ggrid, 256, GEMM_SMEM>>>(bq, bk, bv);

    // Attention
    dim3 agrid(BATCH * HEADS, SEQ / 128);        // (32, 16)
    flash_attn_mma<<<agrid, 256, ATT_SMEM>>>();

    // Output projection
    dim3 ogrid(D_MODEL / BN, M_TOTAL / BM);      // (8, 32)
    gemm_o<<<ogrid, 256, GEMM_SMEM>>>(bo, out);
}